// round 2
// baseline (speedup 1.0000x reference)
#include <cuda_runtime.h>

// SplineInter: 2M points, bicubic B-spline on padded 1028x1028 fp32 grid.
// out[n] = sum_{j,k in [-1..2]} coeffs[(2+P0+j)*1028 + (2+P1+k)] * w0[j] * w1[k]
// with xn = x*1024 - 0.5, P = floor(xn), t = xn - P, and cubic B-spline pieces:
//   w[-1] = (1-t)^3
//   w[ 0] = (3t-6)t^2 + 4
//   w[+1] = -(3t+3)(t-1)^2 + 4   ( = -(3(t-1)+6)(t-1)^2 + 4 )
//   w[+2] = t^3

#define NPTS   2097152
#define I1     1028          // row stride of padded grid
#define SCALE  1024.0f

__device__ __forceinline__ void bspline_w(float t, float w[4]) {
    float omt = 1.0f - t;
    float t2  = t * t;
    float u   = t - 1.0f;
    w[0] = omt * omt * omt;
    w[1] = (3.0f * t - 6.0f) * t2 + 4.0f;
    w[2] = -(3.0f * t + 3.0f) * (u * u) + 4.0f;
    w[3] = t * t2;
}

__global__ __launch_bounds__(256) void spline_kernel(
    const float2* __restrict__ x,      // [N] (pairs)
    const float*  __restrict__ coeffs, // [1028*1028]
    float*        __restrict__ out)    // [N]
{
    int n = blockIdx.x * blockDim.x + threadIdx.x;
    if (n >= NPTS) return;

    float2 p = x[n];
    float xn0 = p.x * SCALE - 0.5f;
    float xn1 = p.y * SCALE - 0.5f;

    bool valid = (xn0 > -2.0f) & (xn0 < 1024.0f) & (xn1 > -2.0f) & (xn1 < 1024.0f);

    float f0 = floorf(xn0);
    float f1 = floorf(xn1);
    int P0 = (int)f0;
    int P1 = (int)f1;
    float t0 = xn0 - f0;
    float t1 = xn1 - f1;

    float w0[4], w1[4];
    bspline_w(t0, w0);
    bspline_w(t1, w1);

    // base of the 4x4 stencil (top-left): row = 2+P0-1, col = 2+P1-1
    int base = (P0 + 1) * I1 + (P1 + 1);
    const float* g = coeffs + base;

    // Batch all 16 gathers first -> maximize MLP to hide L2 latency.
    float c[4][4];
#pragma unroll
    for (int j = 0; j < 4; j++) {
#pragma unroll
        for (int k = 0; k < 4; k++) {
            c[j][k] = __ldg(g + j * I1 + k);
        }
    }

    float acc = 0.0f;
#pragma unroll
    for (int j = 0; j < 4; j++) {
        float r = c[j][0] * w1[0];
        r = fmaf(c[j][1], w1[1], r);
        r = fmaf(c[j][2], w1[2], r);
        r = fmaf(c[j][3], w1[3], r);
        acc = fmaf(w0[j], r, acc);
    }

    out[n] = valid ? acc : 0.0f;
}

extern "C" void kernel_launch(void* const* d_in, const int* in_sizes, int n_in,
                              void* d_out, int out_size) {
    const float2* x      = (const float2*)d_in[0];
    const float*  coeffs = (const float*)d_in[1];
    float*        out    = (float*)d_out;

    const int threads = 256;
    const int blocks  = NPTS / threads;
    spline_kernel<<<blocks, threads>>>(x, coeffs, out);
}

// round 5
// speedup vs baseline: 1.1093x; 1.1093x over previous
#include <cuda_runtime.h>

// SplineInter: 2M points, bicubic B-spline on padded 1028x1028 fp32 grid.
// out[n] = sum_{j,k in [-1..2]} coeffs[(2+P0+j)*1028 + (2+P1+k)] * w0[j] * w1[k]
// with xn = x*1024 - 0.5, P = floor(xn), t = xn - P, and cubic B-spline pieces:
//   w[-1] = (1-t)^3
//   w[ 0] = (3t-6)t^2 + 4
//   w[+1] = -(3t+3)(t-1)^2 + 4   ( = -(3(t-1)+6)(t-1)^2 + 4 )
//   w[+2] = t^3

#define NPTS   2097152
#define I1     1028          // row stride of padded grid
#define SCALE  1024.0f

__device__ __forceinline__ void bspline_w(float t, float w[4]) {
    float omt = 1.0f - t;
    float t2  = t * t;
    float u   = t - 1.0f;
    w[0] = omt * omt * omt;
    w[1] = (3.0f * t - 6.0f) * t2 + 4.0f;
    w[2] = -(3.0f * t + 3.0f) * (u * u) + 4.0f;
    w[3] = t * t2;
}

__global__ __launch_bounds__(256) void spline_kernel(
    const float2* __restrict__ x,      // [N] (pairs)
    const float*  __restrict__ coeffs, // [1028*1028]
    float*        __restrict__ out)    // [N]
{
    int n = blockIdx.x * blockDim.x + threadIdx.x;
    if (n >= NPTS) return;

    float2 p = x[n];
    float xn0 = p.x * SCALE - 0.5f;
    float xn1 = p.y * SCALE - 0.5f;

    bool valid = (xn0 > -2.0f) & (xn0 < 1024.0f) & (xn1 > -2.0f) & (xn1 < 1024.0f);

    float f0 = floorf(xn0);
    float f1 = floorf(xn1);
    int P0 = (int)f0;
    int P1 = (int)f1;
    float t0 = xn0 - f0;
    float t1 = xn1 - f1;

    float w0[4], w1[4];
    bspline_w(t0, w0);
    bspline_w(t1, w1);

    // base of the 4x4 stencil (top-left): row = 2+P0-1, col = 2+P1-1
    int base = (P0 + 1) * I1 + (P1 + 1);
    const float* g = coeffs + base;

    // Batch all 16 gathers first -> maximize MLP to hide L2 latency.
    float c[4][4];
#pragma unroll
    for (int j = 0; j < 4; j++) {
#pragma unroll
        for (int k = 0; k < 4; k++) {
            c[j][k] = __ldg(g + j * I1 + k);
        }
    }

    float acc = 0.0f;
#pragma unroll
    for (int j = 0; j < 4; j++) {
        float r = c[j][0] * w1[0];
        r = fmaf(c[j][1], w1[1], r);
        r = fmaf(c[j][2], w1[2], r);
        r = fmaf(c[j][3], w1[3], r);
        acc = fmaf(w0[j], r, acc);
    }

    out[n] = valid ? acc : 0.0f;
}

extern "C" void kernel_launch(void* const* d_in, const int* in_sizes, int n_in,
                              void* d_out, int out_size) {
    const float2* x      = (const float2*)d_in[0];
    const float*  coeffs = (const float*)d_in[1];
    float*        out    = (float*)d_out;

    const int threads = 256;
    const int blocks  = NPTS / threads;
    spline_kernel<<<blocks, threads>>>(x, coeffs, out);
}

// round 6
// speedup vs baseline: 1.1365x; 1.0246x over previous
#include <cuda_runtime.h>

// SplineInter: 2M points, bicubic B-spline on padded 1028x1028 fp32 grid.
// R5: replace 16x divergent LDG.32 with 8x LDG.128 (16B-aligned row segments)
// to halve L1tex wavefront count; shift absorbed into 7-wide weight vector.

#define NPTS   2097152
#define I1     1028            // row stride of padded grid (floats)
#define I1V4   257             // row stride in float4 (1028/4)
#define SCALE  1024.0f

__device__ __forceinline__ void bspline_w(float t, float w[4]) {
    float omt = 1.0f - t;
    float t2  = t * t;
    float u   = t - 1.0f;
    w[0] = omt * omt * omt;
    w[1] = (3.0f * t - 6.0f) * t2 + 4.0f;
    w[2] = -(3.0f * t + 3.0f) * (u * u) + 4.0f;
    w[3] = t * t2;
}

__global__ __launch_bounds__(256) void spline_kernel(
    const float2* __restrict__ x,      // [N] point pairs
    const float*  __restrict__ coeffs, // [1028*1028]
    float*        __restrict__ out)    // [N]
{
    int n = blockIdx.x * blockDim.x + threadIdx.x;
    if (n >= NPTS) return;

    float2 p = x[n];
    float xn0 = p.x * SCALE - 0.5f;
    float xn1 = p.y * SCALE - 0.5f;

    bool valid = (xn0 > -2.0f) & (xn0 < 1024.0f) & (xn1 > -2.0f) & (xn1 < 1024.0f);

    float f0 = floorf(xn0);
    float f1 = floorf(xn1);
    int P0 = (int)f0;
    int P1 = (int)f1;
    float t0 = xn0 - f0;
    float t1 = xn1 - f1;

    float w0[4], w1[4];
    bspline_w(t0, w0);
    bspline_w(t1, w1);

    // stencil top-left: row r = P0+1 (in [0,1023+... up to 1024? no: P0+1..P0+4
    // in [0,1027]), col c = P1+1 in [0,1024]
    int r  = P0 + 1;
    int c  = P1 + 1;
    int c0 = c & ~3;          // 16B-aligned start column
    int ko = c - c0;          // shift 0..3

    // float4 pointer to (r, c0); both loads per row are LDG.E.128, 16B aligned.
    const float4* rowp = (const float4*)(coeffs + r * I1 + c0);
    // Edge: c0==1024 only when ko==0 (high-half weights all zero) -> make the
    // second load alias the first so it never reads past the array end.
    int off_b = (c0 == 1024) ? 0 : 1;

    // Batch all 8 wide gathers -> max MLP to hide L2 latency (~250 cyc).
    float4 a[4], b[4];
#pragma unroll
    for (int j = 0; j < 4; j++) {
        a[j] = __ldg(rowp + j * I1V4);
        b[j] = __ldg(rowp + j * I1V4 + off_b);
    }

    // Shifted 7-wide weight vector: wv[i] = w1[i-ko] for i-ko in [0,3], else 0.
    // Static SELs only (no dynamic register indexing).
    bool k0 = (ko == 0), k1 = (ko == 1), k2 = (ko == 2);
    float wv0 = k0 ? w1[0] : 0.0f;
    float wv1 = k0 ? w1[1] : (k1 ? w1[0] : 0.0f);
    float wv2 = k0 ? w1[2] : (k1 ? w1[1] : (k2 ? w1[0] : 0.0f));
    float wv3 = k0 ? w1[3] : (k1 ? w1[2] : (k2 ? w1[1] : w1[0]));
    float wv4 = k1 ? w1[3] : (k2 ? w1[2] : (k0 ? 0.0f : w1[1]));
    float wv5 = k2 ? w1[3] : ((k0 | k1) ? 0.0f : w1[2]);
    float wv6 = (k0 | k1 | k2) ? 0.0f : w1[3];

    float acc = 0.0f;
#pragma unroll
    for (int j = 0; j < 4; j++) {
        float s;
        s = a[j].x * wv0;
        s = fmaf(a[j].y, wv1, s);
        s = fmaf(a[j].z, wv2, s);
        s = fmaf(a[j].w, wv3, s);
        s = fmaf(b[j].x, wv4, s);
        s = fmaf(b[j].y, wv5, s);
        s = fmaf(b[j].z, wv6, s);
        acc = fmaf(w0[j], s, acc);
    }

    out[n] = valid ? acc : 0.0f;
}

extern "C" void kernel_launch(void* const* d_in, const int* in_sizes, int n_in,
                              void* d_out, int out_size) {
    const float2* x      = (const float2*)d_in[0];
    const float*  coeffs = (const float*)d_in[1];
    float*        out    = (float*)d_out;

    const int threads = 256;
    const int blocks  = NPTS / threads;
    spline_kernel<<<blocks, threads>>>(x, coeffs, out);
}